// round 16
// baseline (speedup 1.0000x reference)
#include <cuda_runtime.h>
#include <cuda_fp16.h>
#include <cstdint>
#include <math.h>

#define D_  1024
#define V_  50257
#define VP_ 50304          // V padded to multiple of 128 (393 tiles)
#define B_  2
#define S_  2048
#define S1_ 2049
#define T_  4096
#define NCHUNK 128
#define CLEN   16

#define BM 128
#define BN 128
#define BKH 32             // halves per k-tile
#define STRH 40            // smem row stride in halves
#define STAGES 4
#define STG_HALVES ((BM + BN) * STRH)              // 10240 halves / 20480 B
#define NT_LOG (VP_ / BN)                          // 393 N-tiles in logits GEMM

// ---------------- scratch (static device globals; no runtime allocation) ----
__device__ __half g_h1h[(size_t)T_ * D_];
__device__ float  g_hg [(size_t)T_ * 2 * D_];
__device__ float  g_cb [(size_t)T_ * D_];
__device__ float  g_vb [(size_t)T_ * D_];
__device__ float  g_Ac [B_ * NCHUNK * D_];
__device__ float  g_Bc [B_ * NCHUNK * D_];
__device__ float  g_carry[B_ * NCHUNK * D_];
__device__ __half g_h2h[(size_t)T_ * D_];
__device__ __half g_mlp1h[(size_t)T_ * 4 * D_];
__device__ float  g_h3 [(size_t)T_ * D_];
__device__ __half g_h4h[(size_t)T_ * D_];
__device__ float  g_lp [T_];
__device__ float2 g_lpart[(size_t)T_ * NT_LOG];
// transposed (N-major) fp16 weights
__device__ __half g_whgT[(size_t)(2 * D_) * D_];
__device__ __half g_w1T [(size_t)(4 * D_) * D_];
__device__ __half g_w2T [(size_t)D_ * (4 * D_)];
__device__ __half g_wlogT[(size_t)VP_ * D_];

// ---------------- helpers ---------------------------------------------------
__device__ __forceinline__ float gelu_exact(float x) {
    return 0.5f * x * (1.0f + erff(x * 0.7071067811865476f));
}

__device__ __forceinline__ uint32_t cvta_s(const void* p) {
    return (uint32_t)__cvta_generic_to_shared(p);
}

#define CP16(dst, src) \
    asm volatile("cp.async.cg.shared.global [%0], [%1], 16;\n" :: "r"(dst), "l"(src))

__device__ __forceinline__ void mma_f16(float c[4], const uint32_t a[4], const uint32_t b[2]) {
    asm volatile(
        "mma.sync.aligned.m16n8k16.row.col.f32.f16.f16.f32 "
        "{%0,%1,%2,%3}, {%4,%5,%6,%7}, {%8,%9}, {%0,%1,%2,%3};"
        : "+f"(c[0]), "+f"(c[1]), "+f"(c[2]), "+f"(c[3])
        : "r"(a[0]), "r"(a[1]), "r"(a[2]), "r"(a[3]), "r"(b[0]), "r"(b[1]));
}

// online logsumexp merge: (m,s) <- (m,s) + (m2,s2)   (fast exp: err ~5e-7)
__device__ __forceinline__ void lmerge(float& m, float& s, float m2, float s2) {
    float M = fmaxf(m, m2);
    if (M == -INFINITY) { m = M; s = 0.f; return; }
    s = s * __expf(m - M) + s2 * __expf(m2 - M);
    m = M;
}

// ---------------- weight transpose fp32[K][N] -> fp16[Npad][K] --------------
__global__ void transposeW(const float* __restrict__ in, __half* __restrict__ outp,
                           int K, int N, int Npad)
{
    __shared__ float t[32][33];
    int nb = blockIdx.x * 32, kb = blockIdx.y * 32;
    int tx = threadIdx.x, ty = threadIdx.y;     // 32 x 8
    #pragma unroll
    for (int p = 0; p < 32; p += 8) {
        int k = kb + ty + p, n = nb + tx;
        float v = (n < N) ? in[(size_t)k * N + n] : 0.f;
        t[ty + p][tx] = v;
    }
    __syncthreads();
    int tid = ty * 32 + tx;
    #pragma unroll
    for (int it = 0; it < 2; it++) {
        int item = tid + it * 256;          // 0..511
        int nl = item >> 4;                 // 0..31
        int kp = item & 15;                 // 0..15
        __half2 hv = __floats2half2_rn(t[2 * kp][nl], t[2 * kp + 1][nl]);
        *(__half2*)(outp + (size_t)(nb + nl) * K + kb + 2 * kp) = hv;
    }
}

// ---------------- pipelined fp16 GEMM, CTA 128x128, warp 64x32 --------------
// C[M,N] = A[M,K] @ Bt[N,K]^T  (+bias, gelu, +resid; fp32 or fp16 out)
// __launch_bounds__(256, 2): force regs <= 128 so 2 CTAs/SM co-reside.
// DO_LOSS=1: inline per-row logsumexp partials during the store pass.
// RESID_HALF: compile-time residual dtype (no runtime flag -> no reg pollution).
template<int DO_LOSS, int RESID_HALF>
__global__ __launch_bounds__(256, 2)
void gemm_f16(const __half* __restrict__ A, const __half* __restrict__ Bt,
              void* __restrict__ Cout, int M, int N, int K,
              const float* __restrict__ bias, const void* __restrict__ resid,
              int do_gelu, int out_half, float2* __restrict__ lpart)
{
    extern __shared__ __half smemh[];

    const int tid  = threadIdx.x;
    const int lane = tid & 31;
    const int warp = tid >> 5;
    const int wm   = warp >> 2;      // 0..1
    const int wn   = warp & 3;       // 0..3
    const int g    = lane >> 2;      // 0..7
    const int tg   = lane & 3;       // 0..3

    const int m0 = blockIdx.x * BM;
    const int n0 = blockIdx.y * BN;
    const int KT = K / BKH;

    float acc[4][4][4];
    #pragma unroll
    for (int mi = 0; mi < 4; mi++)
        #pragma unroll
        for (int ni = 0; ni < 4; ni++)
            #pragma unroll
            for (int r = 0; r < 4; r++) acc[mi][ni][r] = 0.f;

    // fill: 256 rows (A:0..127, B:128..255) x 4 chunks of 16B
    auto fill = [&](int t) {
        __half* base = smemh + (t & (STAGES - 1)) * STG_HALVES;
        uint32_t sb = cvta_s(base);
        #pragma unroll
        for (int p = 0; p < 4; p++) {
            int idx = tid + p * 256;
            int row = idx >> 2, c = idx & 3;
            const __half* src = (row < BM)
                ? A  + (size_t)(m0 + row) * K + t * BKH + c * 8
                : Bt + (size_t)(n0 + row - BM) * K + t * BKH + c * 8;
            CP16(sb + row * (STRH * 2) + c * 16, src);
        }
        asm volatile("cp.async.commit_group;\n");
    };

    #pragma unroll
    for (int t = 0; t < STAGES - 1; t++) fill(t);

    for (int it = 0; it < KT; it++) {
        asm volatile("cp.async.wait_group %0;\n" :: "n"(STAGES - 2));
        __syncthreads();

        int nk = it + STAGES - 1;
        if (nk < KT) fill(nk);
        else asm volatile("cp.async.commit_group;\n");

        const __half* As = smemh + (it & (STAGES - 1)) * STG_HALVES;
        const __half* Bs = As + BM * STRH;

        #pragma unroll
        for (int kc = 0; kc < 2; kc++) {
            uint32_t af[4][4], bf[4][2];
            #pragma unroll
            for (int mi = 0; mi < 4; mi++) {
                int mb = wm * 64 + mi * 16;
                const __half* pa = As + (mb + g) * STRH + kc * 16 + 2 * tg;
                af[mi][0] = *(const uint32_t*)(pa);
                af[mi][1] = *(const uint32_t*)(pa + 8 * STRH);
                af[mi][2] = *(const uint32_t*)(pa + 8);
                af[mi][3] = *(const uint32_t*)(pa + 8 * STRH + 8);
            }
            #pragma unroll
            for (int ni = 0; ni < 4; ni++) {
                int nb = wn * 32 + ni * 8;
                const __half* pb = Bs + (nb + g) * STRH + kc * 16 + 2 * tg;
                bf[ni][0] = *(const uint32_t*)(pb);
                bf[ni][1] = *(const uint32_t*)(pb + 8);
            }
            #pragma unroll
            for (int mi = 0; mi < 4; mi++)
                #pragma unroll
                for (int ni = 0; ni < 4; ni++)
                    mma_f16(acc[mi][ni], af[mi], bf[ni]);
        }
    }

    float2* lsm = (float2*)smemh;              // loss staging (aliases stage 0)
    if (DO_LOSS) __syncthreads();              // all warps past last tile reads

    // ---- epilogue: store (+ inline loss partials when DO_LOSS) ----
    #pragma unroll
    for (int mi = 0; mi < 4; mi++) {
        #pragma unroll
        for (int rr = 0; rr < 2; rr++) {
            int row = m0 + wm * 64 + mi * 16 + g + rr * 8;
            float lm = -INFINITY, ls = 0.f;
            #pragma unroll
            for (int ni = 0; ni < 4; ni++) {
                int col = n0 + wn * 32 + ni * 8 + tg * 2;
                float o0 = acc[mi][ni][rr * 2 + 0];
                float o1 = acc[mi][ni][rr * 2 + 1];
                if (bias)    { o0 += bias[col]; o1 += bias[col + 1]; }
                if (do_gelu) { o0 = gelu_exact(o0); o1 = gelu_exact(o1); }
                if (resid) {
                    if (RESID_HALF) {
                        __half2 rv = *(const __half2*)((const __half*)resid +
                                                       (size_t)row * N + col);
                        o0 += __half2float(rv.x); o1 += __half2float(rv.y);
                    } else {
                        o0 += ((const float*)resid)[(size_t)row * N + col];
                        o1 += ((const float*)resid)[(size_t)row * N + col + 1];
                    }
                }
                if (out_half) {
                    *(__half2*)((__half*)Cout + (size_t)row * N + col) =
                        __floats2half2_rn(o0, o1);
                } else {
                    float* C = (float*)Cout;
                    if (col < N)     C[(size_t)row * N + col]     = o0;
                    if (col + 1 < N) C[(size_t)row * N + col + 1] = o1;
                }
                if (DO_LOSS) {
                    if (col < N) {
                        if (o0 > lm) { ls = ls * __expf(lm - o0) + 1.f; lm = o0; }
                        else         { ls += __expf(o0 - lm); }
                    }
                    if (col + 1 < N) {
                        if (o1 > lm) { ls = ls * __expf(lm - o1) + 1.f; lm = o1; }
                        else         { ls += __expf(o1 - lm); }
                    }
                }
            }
            if (DO_LOSS) {
                #pragma unroll
                for (int d = 1; d <= 2; d <<= 1) {
                    float m2 = __shfl_xor_sync(0xFFFFFFFF, lm, d);
                    float s2 = __shfl_xor_sync(0xFFFFFFFF, ls, d);
                    lmerge(lm, ls, m2, s2);
                }
                if (tg == 0) {
                    int srow = wm * 64 + mi * 16 + g + rr * 8;
                    lsm[srow * 4 + wn] = make_float2(lm, ls);
                }
            }
        }
    }

    if (DO_LOSS) {
        __syncthreads();
        if (tid < 128) {
            float m = -INFINITY, s = 0.f;
            #pragma unroll
            for (int w = 0; w < 4; w++) {
                float2 p = lsm[tid * 4 + w];
                lmerge(m, s, p.x, p.y);
            }
            lpart[(size_t)(m0 + tid) * NT_LOG + blockIdx.y] = make_float2(m, s);
        }
    }
}

// ---------------- embedding gather + RMSNorm (fp16 out) ---------------------
__global__ void embed_rms(const int* __restrict__ x, const float* __restrict__ emb,
                          const float* __restrict__ gamma, __half* __restrict__ h1h)
{
    int tk = blockIdx.x;
    int b = tk >> 11, t = tk & 2047;
    int id = x[b * S1_ + t];
    const float4* row = (const float4*)(emb + (size_t)id * D_);
    int tid = threadIdx.x;
    float4 v = row[tid];
    float ss = v.x * v.x + v.y * v.y + v.z * v.z + v.w * v.w;
    __shared__ float red[256];
    red[tid] = ss; __syncthreads();
    for (int st = 128; st > 0; st >>= 1) {
        if (tid < st) red[tid] += red[tid + st];
        __syncthreads();
    }
    float scale = 32.0f / fmaxf(sqrtf(red[0]), 1e-12f);
    float4 gv = ((const float4*)gamma)[tid];
    __half2 p0 = __floats2half2_rn(v.x * scale * (gv.x + 1.f), v.y * scale * (gv.y + 1.f));
    __half2 p1 = __floats2half2_rn(v.z * scale * (gv.z + 1.f), v.w * scale * (gv.w + 1.f));
    ((__half2*)(h1h + (size_t)tk * D_))[tid * 2]     = p0;
    ((__half2*)(h1h + (size_t)tk * D_))[tid * 2 + 1] = p1;
}

__global__ void rms_rows(const float* __restrict__ in, const float* __restrict__ gamma,
                         __half* __restrict__ outp)
{
    int tk = blockIdx.x;
    int tid = threadIdx.x;
    float4 v = ((const float4*)(in + (size_t)tk * D_))[tid];
    float ss = v.x * v.x + v.y * v.y + v.z * v.z + v.w * v.w;
    __shared__ float red[256];
    red[tid] = ss; __syncthreads();
    for (int st = 128; st > 0; st >>= 1) {
        if (tid < st) red[tid] += red[tid + st];
        __syncthreads();
    }
    float scale = 32.0f / fmaxf(sqrtf(red[0]), 1e-12f);
    float4 gv = ((const float4*)gamma)[tid];
    __half2 p0 = __floats2half2_rn(v.x * scale * (gv.x + 1.f), v.y * scale * (gv.y + 1.f));
    __half2 p1 = __floats2half2_rn(v.z * scale * (gv.z + 1.f), v.w * scale * (gv.w + 1.f));
    ((__half2*)(outp + (size_t)tk * D_))[tid * 2]     = p0;
    ((__half2*)(outp + (size_t)tk * D_))[tid * 2 + 1] = p1;
}

// ---------------- minGRU chunked linear-recurrence scan ---------------------
// Gates computed ONCE in phase1 (fp32 c,v stored); phase3 is MUFU-free.
__device__ __forceinline__ void gate_cv(float hid, float gate, float& c, float& v) {
    float e = __expf(gate);
    c = __fdividef(1.f, 1.f + e);
    float z = 1.f - c;
    float gg = (hid >= 0.f) ? (hid + 0.5f)
                            : __fdividef(1.f, 1.f + __expf(-hid));
    v = z * gg;
}

__global__ void scan_phase1(const float* __restrict__ hg,
                            float* __restrict__ cb, float* __restrict__ vb,
                            float* __restrict__ Ac, float* __restrict__ Bc)
{
    int gt = blockIdx.x * blockDim.x + threadIdx.x;
    int d = gt & (D_ - 1);
    int chunk = (gt >> 10) & (NCHUNK - 1);
    int b = gt >> 17;
    float Aacc = 1.f, Bacc = 0.f;
    #pragma unroll 4
    for (int s = 0; s < CLEN; s++) {
        int t = chunk * CLEN + s;
        size_t row = (size_t)(b * S_ + t) * (2 * D_);
        float c, v;
        gate_cv(hg[row + d], hg[row + D_ + d], c, v);
        size_t o = (size_t)(b * S_ + t) * D_ + d;
        cb[o] = c; vb[o] = v;
        Bacc = c * Bacc + v;
        Aacc *= c;
    }
    int idx = (b * NCHUNK + chunk) * D_ + d;
    Ac[idx] = Aacc; Bc[idx] = Bacc;
}

__global__ void scan_phase2(const float* __restrict__ Ac, const float* __restrict__ Bc,
                            float* __restrict__ carry)
{
    int gt = blockIdx.x * blockDim.x + threadIdx.x;
    int d = gt & (D_ - 1);
    int b = gt >> 10;
    float h = 0.f;
    for (int chunk = 0; chunk < NCHUNK; chunk++) {
        int idx = (b * NCHUNK + chunk) * D_ + d;
        carry[idx] = h;
        h = Ac[idx] * h + Bc[idx];
    }
}

__global__ void scan_phase3(const float* __restrict__ cb, const float* __restrict__ vb,
                            const float* __restrict__ carry,
                            const __half* __restrict__ h1h,
                            __half* __restrict__ h2h, float* __restrict__ next_hidden)
{
    int gt = blockIdx.x * blockDim.x + threadIdx.x;
    int d = gt & (D_ - 1);
    int chunk = (gt >> 10) & (NCHUNK - 1);
    int b = gt >> 17;
    float h = carry[(b * NCHUNK + chunk) * D_ + d];
    #pragma unroll 4
    for (int s = 0; s < CLEN; s++) {
        int t = chunk * CLEN + s;
        size_t o = (size_t)(b * S_ + t) * D_ + d;
        h = cb[o] * h + vb[o];
        float hv = h + __half2float(h1h[o]);
        h2h[o] = __float2half_rn(hv);
        if (t == S_ - 1) next_hidden[b * D_ + d] = h;
    }
}

// ---------------- loss reduction over N-tile partials -----------------------
__global__ void loss_reduce(const float2* __restrict__ part,
                            const float* __restrict__ logits,
                            const int* __restrict__ x, float* __restrict__ lp)
{
    int tk = blockIdx.x;
    int tid = threadIdx.x;       // 256 threads
    float m = -INFINITY, s = 0.f;
    for (int i = tid; i < NT_LOG; i += 256) {
        float2 p = part[(size_t)tk * NT_LOG + i];
        lmerge(m, s, p.x, p.y);
    }
    __shared__ float sm[256], ssum[256];
    sm[tid] = m; ssum[tid] = s; __syncthreads();
    for (int st = 128; st > 0; st >>= 1) {
        if (tid < st) {
            lmerge(sm[tid], ssum[tid], sm[tid + st], ssum[tid + st]);
        }
        __syncthreads();
    }
    if (tid == 0) {
        int b = tk >> 11, t = tk & 2047;
        int lab = x[b * S1_ + t + 1];
        lp[tk] = logits[(size_t)tk * V_ + lab] - (sm[0] + logf(ssum[0]));
    }
}

__global__ void loss_final(const float* __restrict__ lp, float* __restrict__ outp)
{
    int tid = threadIdx.x;
    float s = 0.f;
    for (int i = tid; i < T_; i += 256) s += lp[i];
    __shared__ float red[256];
    red[tid] = s; __syncthreads();
    for (int st = 128; st > 0; st >>= 1) {
        if (tid < st) red[tid] += red[tid + st];
        __syncthreads();
    }
    if (tid == 0) outp[0] = -red[0] / (float)T_;
}

// ---------------- launch ----------------------------------------------------
extern "C" void kernel_launch(void* const* d_in, const int* in_sizes, int n_in,
                              void* d_out, int out_size)
{
    const int*   x       = (const int*)  d_in[0];
    const float* emb     = (const float*)d_in[1];
    const float* gamma1  = (const float*)d_in[2];
    const float* W_hg    = (const float*)d_in[3];
    const float* W1      = (const float*)d_in[4];
    const float* b1      = (const float*)d_in[5];
    const float* W2      = (const float*)d_in[6];
    const float* b2      = (const float*)d_in[7];
    const float* gamma2  = (const float*)d_in[8];
    const float* Wlog    = (const float*)d_in[9];
    float* out = (float*)d_out;

    float *hg, *cb, *vb, *Ac, *Bc, *carry, *h3, *lp;
    float2* lpart;
    __half *h1h, *h2h, *mlp1h, *h4h, *whgT, *w1T, *w2T, *wlogT;
    cudaGetSymbolAddress((void**)&h1h,   g_h1h);
    cudaGetSymbolAddress((void**)&hg,    g_hg);
    cudaGetSymbolAddress((void**)&cb,    g_cb);
    cudaGetSymbolAddress((void**)&vb,    g_vb);
    cudaGetSymbolAddress((void**)&Ac,    g_Ac);
    cudaGetSymbolAddress((void**)&Bc,    g_Bc);
    cudaGetSymbolAddress((void**)&carry, g_carry);
    cudaGetSymbolAddress((void**)&h2h,   g_h2h);
    cudaGetSymbolAddress((void**)&mlp1h, g_mlp1h);
    cudaGetSymbolAddress((void**)&h3,    g_h3);
    cudaGetSymbolAddress((void**)&h4h,   g_h4h);
    cudaGetSymbolAddress((void**)&lp,    g_lp);
    cudaGetSymbolAddress((void**)&lpart, g_lpart);
    cudaGetSymbolAddress((void**)&whgT,  g_whgT);
    cudaGetSymbolAddress((void**)&w1T,   g_w1T);
    cudaGetSymbolAddress((void**)&w2T,   g_w2T);
    cudaGetSymbolAddress((void**)&wlogT, g_wlogT);

    const int smem_bytes = STAGES * STG_HALVES * (int)sizeof(__half);   // 81920
    static bool init_done = false;
    static cudaStream_t s2;
    static cudaEvent_t ev_fork, ev_whg, ev_join;
    if (!init_done) {
        cudaFuncSetAttribute((const void*)gemm_f16<0,0>,
                             cudaFuncAttributeMaxDynamicSharedMemorySize, smem_bytes);
        cudaFuncSetAttribute((const void*)gemm_f16<0,1>,
                             cudaFuncAttributeMaxDynamicSharedMemorySize, smem_bytes);
        cudaFuncSetAttribute((const void*)gemm_f16<1,0>,
                             cudaFuncAttributeMaxDynamicSharedMemorySize, smem_bytes);
        cudaStreamCreateWithFlags(&s2, cudaStreamNonBlocking);
        cudaEventCreateWithFlags(&ev_fork, cudaEventDisableTiming);
        cudaEventCreateWithFlags(&ev_whg,  cudaEventDisableTiming);
        cudaEventCreateWithFlags(&ev_join, cudaEventDisableTiming);
        init_done = true;
    }

    float* logits      = out + 1;
    float* next_hidden = out + 1 + (size_t)T_ * V_;

    dim3 tb(32, 8);

    // fork: ALL weight conversions on s2, overlapped with embed/scan chain
    cudaEventRecord(ev_fork, 0);
    cudaStreamWaitEvent(s2, ev_fork, 0);
    transposeW<<<dim3((2 * D_) / 32, D_ / 32), tb, 0, s2>>>(W_hg, whgT, D_, 2 * D_, 2 * D_);
    cudaEventRecord(ev_whg, s2);
    transposeW<<<dim3((4 * D_) / 32, D_ / 32), tb, 0, s2>>>(W1,   w1T,  D_,     4 * D_, 4 * D_);
    transposeW<<<dim3(D_ / 32, (4 * D_) / 32), tb, 0, s2>>>(W2,   w2T,  4 * D_, D_,     D_);
    transposeW<<<dim3(VP_ / 32, D_ / 32),      tb, 0, s2>>>(Wlog, wlogT, D_,    V_,     VP_);
    cudaEventRecord(ev_join, s2);

    embed_rms<<<T_, 256>>>(x, emb, gamma1, h1h);

    // hg = h1 @ W_hg   [4096 x 2048] fp32 out  (needs whgT)
    cudaStreamWaitEvent(0, ev_whg, 0);
    gemm_f16<0,0><<<dim3(T_ / BM, (2 * D_) / BN), 256, smem_bytes>>>(
        h1h, whgT, hg, T_, 2 * D_, D_, nullptr, nullptr, 0, 0, nullptr);

    scan_phase1<<<(B_ * NCHUNK * D_) / 256, 256>>>(hg, cb, vb, Ac, Bc);
    scan_phase2<<<(B_ * D_) / 256, 256>>>(Ac, Bc, carry);
    scan_phase3<<<(B_ * NCHUNK * D_) / 256, 256>>>(cb, vb, carry, h1h, h2h, next_hidden);

    // join before first use of w1T/w2T/wlogT
    cudaStreamWaitEvent(0, ev_join, 0);

    // mlp1 = gelu(h2 @ W1 + b1)   [4096 x 4096] fp16 out
    gemm_f16<0,0><<<dim3(T_ / BM, (4 * D_) / BN), 256, smem_bytes>>>(
        h2h, w1T, mlp1h, T_, 4 * D_, D_, b1, nullptr, 1, 1, nullptr);

    // h3 = mlp1 @ W2 + b2 + h2    [4096 x 1024] fp32 out, fp16 residual
    gemm_f16<0,1><<<dim3(T_ / BM, D_ / BN), 256, smem_bytes>>>(
        mlp1h, w2T, h3, T_, D_, 4 * D_, b2, h2h, 0, 0, nullptr);

    rms_rows<<<T_, 256>>>(h3, gamma2, h4h);

    // logits = h4 @ W_logits  [4096 x 50257] fp32 out + inline loss partials
    gemm_f16<1,0><<<dim3(T_ / BM, VP_ / BN), 256, smem_bytes>>>(
        h4h, wlogT, logits, T_, V_, D_, nullptr, nullptr, 0, 0, lpart);

    loss_reduce<<<T_, 256>>>(lpart, logits, x, lp);
    loss_final<<<1, 256>>>(lp, out);
}

// round 17
// speedup vs baseline: 1.1099x; 1.1099x over previous
#include <cuda_runtime.h>
#include <cuda_fp16.h>
#include <cstdint>
#include <math.h>

#define D_  1024
#define V_  50257
#define VP_ 50304          // V padded to multiple of 128 (393 tiles)
#define B_  2
#define S_  2048
#define S1_ 2049
#define T_  4096
#define NCHUNK 64
#define CLEN   32

#define BM 128
#define BN 128
#define BKH 64             // halves per k-tile (128 B per row)
#define STRH 72            // smem row stride in halves (bank: 36g+tg == 4g+tg mod 32)
#define STAGES 3
#define STG_HALVES ((BM + BN) * STRH)              // 18432 halves / 36864 B
#define NT_LOG (VP_ / BN)                          // 393 N-tiles in logits GEMM

// ---------------- scratch (static device globals; no runtime allocation) ----
__device__ __half g_h1h[(size_t)T_ * D_];
__device__ float  g_hg [(size_t)T_ * 2 * D_];
__device__ float  g_cb [(size_t)T_ * D_];
__device__ float  g_vb [(size_t)T_ * D_];
__device__ float  g_Ac [B_ * NCHUNK * D_];
__device__ float  g_Bc [B_ * NCHUNK * D_];
__device__ float  g_carry[B_ * NCHUNK * D_];
__device__ __half g_h2h[(size_t)T_ * D_];
__device__ __half g_mlp1h[(size_t)T_ * 4 * D_];
__device__ float  g_h3 [(size_t)T_ * D_];
__device__ __half g_h4h[(size_t)T_ * D_];
__device__ float  g_lp [T_];
__device__ float2 g_lpart[(size_t)T_ * NT_LOG];
// transposed (N-major) fp16 weights
__device__ __half g_whgT[(size_t)(2 * D_) * D_];
__device__ __half g_w1T [(size_t)(4 * D_) * D_];
__device__ __half g_w2T [(size_t)D_ * (4 * D_)];
__device__ __half g_wlogT[(size_t)VP_ * D_];

// ---------------- helpers ---------------------------------------------------
__device__ __forceinline__ float gelu_exact(float x) {
    return 0.5f * x * (1.0f + erff(x * 0.7071067811865476f));
}

__device__ __forceinline__ uint32_t cvta_s(const void* p) {
    return (uint32_t)__cvta_generic_to_shared(p);
}

#define CP16(dst, src) \
    asm volatile("cp.async.cg.shared.global [%0], [%1], 16;\n" :: "r"(dst), "l"(src))

__device__ __forceinline__ void mma_f16(float c[4], const uint32_t a[4], const uint32_t b[2]) {
    asm volatile(
        "mma.sync.aligned.m16n8k16.row.col.f32.f16.f16.f32 "
        "{%0,%1,%2,%3}, {%4,%5,%6,%7}, {%8,%9}, {%0,%1,%2,%3};"
        : "+f"(c[0]), "+f"(c[1]), "+f"(c[2]), "+f"(c[3])
        : "r"(a[0]), "r"(a[1]), "r"(a[2]), "r"(a[3]), "r"(b[0]), "r"(b[1]));
}

// online logsumexp merge: (m,s) <- (m,s) + (m2,s2)   (fast exp: err ~5e-7)
__device__ __forceinline__ void lmerge(float& m, float& s, float m2, float s2) {
    float M = fmaxf(m, m2);
    if (M == -INFINITY) { m = M; s = 0.f; return; }
    s = s * __expf(m - M) + s2 * __expf(m2 - M);
    m = M;
}

// ---------------- weight transpose fp32[K][N] -> fp16[Npad][K] --------------
__global__ void transposeW(const float* __restrict__ in, __half* __restrict__ outp,
                           int K, int N, int Npad)
{
    __shared__ float t[32][33];
    int nb = blockIdx.x * 32, kb = blockIdx.y * 32;
    int tx = threadIdx.x, ty = threadIdx.y;     // 32 x 8
    #pragma unroll
    for (int p = 0; p < 32; p += 8) {
        int k = kb + ty + p, n = nb + tx;
        float v = (n < N) ? in[(size_t)k * N + n] : 0.f;
        t[ty + p][tx] = v;
    }
    __syncthreads();
    int tid = ty * 32 + tx;
    #pragma unroll
    for (int it = 0; it < 2; it++) {
        int item = tid + it * 256;          // 0..511
        int nl = item >> 4;                 // 0..31
        int kp = item & 15;                 // 0..15
        __half2 hv = __floats2half2_rn(t[2 * kp][nl], t[2 * kp + 1][nl]);
        *(__half2*)(outp + (size_t)(nb + nl) * K + kb + 2 * kp) = hv;
    }
}

// ---------------- pipelined fp16 GEMM, CTA 128x128, warp 64x32 --------------
// C[M,N] = A[M,K] @ Bt[N,K]^T  (+bias, gelu, +resid; fp32 or fp16 out)
// k-tile 64 halves, 3-stage cp.async ring (110.6 KB smem, 2 CTAs/SM).
// __launch_bounds__(256, 2): force regs <= 128 so 2 CTAs/SM co-reside.
// DO_LOSS=1: inline per-row logsumexp partials during the store pass.
// RESID_HALF: compile-time residual dtype.
template<int DO_LOSS, int RESID_HALF>
__global__ __launch_bounds__(256, 2)
void gemm_f16(const __half* __restrict__ A, const __half* __restrict__ Bt,
              void* __restrict__ Cout, int M, int N, int K,
              const float* __restrict__ bias, const void* __restrict__ resid,
              int do_gelu, int out_half, float2* __restrict__ lpart)
{
    extern __shared__ __half smemh[];

    const int tid  = threadIdx.x;
    const int lane = tid & 31;
    const int warp = tid >> 5;
    const int wm   = warp >> 2;      // 0..1
    const int wn   = warp & 3;       // 0..3
    const int g    = lane >> 2;      // 0..7
    const int tg   = lane & 3;       // 0..3

    const int m0 = blockIdx.x * BM;
    const int n0 = blockIdx.y * BN;
    const int KT = K / BKH;

    float acc[4][4][4];
    #pragma unroll
    for (int mi = 0; mi < 4; mi++)
        #pragma unroll
        for (int ni = 0; ni < 4; ni++)
            #pragma unroll
            for (int r = 0; r < 4; r++) acc[mi][ni][r] = 0.f;

    // fill: 256 rows (A:0..127, B:128..255) x 8 chunks of 16B
    auto fill = [&](int t) {
        int slot = t % STAGES;
        __half* base = smemh + slot * STG_HALVES;
        uint32_t sb = cvta_s(base);
        #pragma unroll
        for (int p = 0; p < 8; p++) {
            int idx = tid + p * 256;
            int row = idx >> 3, c = idx & 7;
            const __half* src = (row < BM)
                ? A  + (size_t)(m0 + row) * K + t * BKH + c * 8
                : Bt + (size_t)(n0 + row - BM) * K + t * BKH + c * 8;
            CP16(sb + row * (STRH * 2) + c * 16, src);
        }
        asm volatile("cp.async.commit_group;\n");
    };

    #pragma unroll
    for (int t = 0; t < STAGES - 1; t++) fill(t);

    for (int it = 0; it < KT; it++) {
        asm volatile("cp.async.wait_group %0;\n" :: "n"(STAGES - 2));
        __syncthreads();

        int nk = it + STAGES - 1;
        if (nk < KT) fill(nk);
        else asm volatile("cp.async.commit_group;\n");

        const __half* As = smemh + (it % STAGES) * STG_HALVES;
        const __half* Bs = As + BM * STRH;

        #pragma unroll
        for (int kc = 0; kc < 4; kc++) {
            uint32_t af[4][4], bf[4][2];
            #pragma unroll
            for (int mi = 0; mi < 4; mi++) {
                int mb = wm * 64 + mi * 16;
                const __half* pa = As + (mb + g) * STRH + kc * 16 + 2 * tg;
                af[mi][0] = *(const uint32_t*)(pa);
                af[mi][1] = *(const uint32_t*)(pa + 8 * STRH);
                af[mi][2] = *(const uint32_t*)(pa + 8);
                af[mi][3] = *(const uint32_t*)(pa + 8 * STRH + 8);
            }
            #pragma unroll
            for (int ni = 0; ni < 4; ni++) {
                int nb = wn * 32 + ni * 8;
                const __half* pb = Bs + (nb + g) * STRH + kc * 16 + 2 * tg;
                bf[ni][0] = *(const uint32_t*)(pb);
                bf[ni][1] = *(const uint32_t*)(pb + 8);
            }
            #pragma unroll
            for (int mi = 0; mi < 4; mi++)
                #pragma unroll
                for (int ni = 0; ni < 4; ni++)
                    mma_f16(acc[mi][ni], af[mi], bf[ni]);
        }
    }

    float2* lsm = (float2*)smemh;              // loss staging (aliases stage 0)
    if (DO_LOSS) __syncthreads();              // all warps past last tile reads

    // ---- epilogue: store (+ inline loss partials when DO_LOSS) ----
    #pragma unroll
    for (int mi = 0; mi < 4; mi++) {
        #pragma unroll
        for (int rr = 0; rr < 2; rr++) {
            int row = m0 + wm * 64 + mi * 16 + g + rr * 8;
            float lm = -INFINITY, ls = 0.f;
            #pragma unroll
            for (int ni = 0; ni < 4; ni++) {
                int col = n0 + wn * 32 + ni * 8 + tg * 2;
                float o0 = acc[mi][ni][rr * 2 + 0];
                float o1 = acc[mi][ni][rr * 2 + 1];
                if (bias)    { o0 += bias[col]; o1 += bias[col + 1]; }
                if (do_gelu) { o0 = gelu_exact(o0); o1 = gelu_exact(o1); }
                if (resid) {
                    if (RESID_HALF) {
                        __half2 rv = *(const __half2*)((const __half*)resid +
                                                       (size_t)row * N + col);
                        o0 += __half2float(rv.x); o1 += __half2float(rv.y);
                    } else {
                        o0 += ((const float*)resid)[(size_t)row * N + col];
                        o1 += ((const float*)resid)[(size_t)row * N + col + 1];
                    }
                }
                if (out_half) {
                    *(__half2*)((__half*)Cout + (size_t)row * N + col) =
                        __floats2half2_rn(o0, o1);
                } else {
                    float* C = (float*)Cout;
                    if (col < N)     C[(size_t)row * N + col]     = o0;
                    if (col + 1 < N) C[(size_t)row * N + col + 1] = o1;
                }
                if (DO_LOSS) {
                    if (col < N) {
                        if (o0 > lm) { ls = ls * __expf(lm - o0) + 1.f; lm = o0; }
                        else         { ls += __expf(o0 - lm); }
                    }
                    if (col + 1 < N) {
                        if (o1 > lm) { ls = ls * __expf(lm - o1) + 1.f; lm = o1; }
                        else         { ls += __expf(o1 - lm); }
                    }
                }
            }
            if (DO_LOSS) {
                #pragma unroll
                for (int d = 1; d <= 2; d <<= 1) {
                    float m2 = __shfl_xor_sync(0xFFFFFFFF, lm, d);
                    float s2 = __shfl_xor_sync(0xFFFFFFFF, ls, d);
                    lmerge(lm, ls, m2, s2);
                }
                if (tg == 0) {
                    int srow = wm * 64 + mi * 16 + g + rr * 8;
                    lsm[srow * 4 + wn] = make_float2(lm, ls);
                }
            }
        }
    }

    if (DO_LOSS) {
        __syncthreads();
        if (tid < 128) {
            float m = -INFINITY, s = 0.f;
            #pragma unroll
            for (int w = 0; w < 4; w++) {
                float2 p = lsm[tid * 4 + w];
                lmerge(m, s, p.x, p.y);
            }
            lpart[(size_t)(m0 + tid) * NT_LOG + blockIdx.y] = make_float2(m, s);
        }
    }
}

// ---------------- embedding gather + RMSNorm (fp16 out) ---------------------
__global__ void embed_rms(const int* __restrict__ x, const float* __restrict__ emb,
                          const float* __restrict__ gamma, __half* __restrict__ h1h)
{
    int tk = blockIdx.x;
    int b = tk >> 11, t = tk & 2047;
    int id = x[b * S1_ + t];
    const float4* row = (const float4*)(emb + (size_t)id * D_);
    int tid = threadIdx.x;
    float4 v = row[tid];
    float ss = v.x * v.x + v.y * v.y + v.z * v.z + v.w * v.w;
    __shared__ float red[256];
    red[tid] = ss; __syncthreads();
    for (int st = 128; st > 0; st >>= 1) {
        if (tid < st) red[tid] += red[tid + st];
        __syncthreads();
    }
    float scale = 32.0f / fmaxf(sqrtf(red[0]), 1e-12f);
    float4 gv = ((const float4*)gamma)[tid];
    __half2 p0 = __floats2half2_rn(v.x * scale * (gv.x + 1.f), v.y * scale * (gv.y + 1.f));
    __half2 p1 = __floats2half2_rn(v.z * scale * (gv.z + 1.f), v.w * scale * (gv.w + 1.f));
    ((__half2*)(h1h + (size_t)tk * D_))[tid * 2]     = p0;
    ((__half2*)(h1h + (size_t)tk * D_))[tid * 2 + 1] = p1;
}

__global__ void rms_rows(const float* __restrict__ in, const float* __restrict__ gamma,
                         __half* __restrict__ outp)
{
    int tk = blockIdx.x;
    int tid = threadIdx.x;
    float4 v = ((const float4*)(in + (size_t)tk * D_))[tid];
    float ss = v.x * v.x + v.y * v.y + v.z * v.z + v.w * v.w;
    __shared__ float red[256];
    red[tid] = ss; __syncthreads();
    for (int st = 128; st > 0; st >>= 1) {
        if (tid < st) red[tid] += red[tid + st];
        __syncthreads();
    }
    float scale = 32.0f / fmaxf(sqrtf(red[0]), 1e-12f);
    float4 gv = ((const float4*)gamma)[tid];
    __half2 p0 = __floats2half2_rn(v.x * scale * (gv.x + 1.f), v.y * scale * (gv.y + 1.f));
    __half2 p1 = __floats2half2_rn(v.z * scale * (gv.z + 1.f), v.w * scale * (gv.w + 1.f));
    ((__half2*)(outp + (size_t)tk * D_))[tid * 2]     = p0;
    ((__half2*)(outp + (size_t)tk * D_))[tid * 2 + 1] = p1;
}

// ---------------- minGRU chunked linear-recurrence scan ---------------------
__device__ __forceinline__ void gate_cv(float hid, float gate, float& c, float& v) {
    float e = __expf(gate);
    c = __fdividef(1.f, 1.f + e);
    float z = 1.f - c;
    float gg = (hid >= 0.f) ? (hid + 0.5f)
                            : __fdividef(1.f, 1.f + __expf(-hid));
    v = z * gg;
}

__global__ void scan_phase1(const float* __restrict__ hg,
                            float* __restrict__ cb, float* __restrict__ vb,
                            float* __restrict__ Ac, float* __restrict__ Bc)
{
    int gt = blockIdx.x * blockDim.x + threadIdx.x;
    int d = gt & (D_ - 1);
    int chunk = (gt >> 10) & (NCHUNK - 1);
    int b = gt >> 16;
    float Aacc = 1.f, Bacc = 0.f;
    for (int s = 0; s < CLEN; s++) {
        int t = chunk * CLEN + s;
        size_t row = (size_t)(b * S_ + t) * (2 * D_);
        float c, v;
        gate_cv(hg[row + d], hg[row + D_ + d], c, v);
        size_t o = (size_t)(b * S_ + t) * D_ + d;
        cb[o] = c; vb[o] = v;
        Bacc = c * Bacc + v;
        Aacc *= c;
    }
    int idx = (b * NCHUNK + chunk) * D_ + d;
    Ac[idx] = Aacc; Bc[idx] = Bacc;
}

__global__ void scan_phase2(const float* __restrict__ Ac, const float* __restrict__ Bc,
                            float* __restrict__ carry)
{
    int gt = blockIdx.x * blockDim.x + threadIdx.x;
    int d = gt & (D_ - 1);
    int b = gt >> 10;
    float h = 0.f;
    for (int chunk = 0; chunk < NCHUNK; chunk++) {
        int idx = (b * NCHUNK + chunk) * D_ + d;
        carry[idx] = h;
        h = Ac[idx] * h + Bc[idx];
    }
}

__global__ void scan_phase3(const float* __restrict__ cb, const float* __restrict__ vb,
                            const float* __restrict__ carry,
                            const __half* __restrict__ h1h,
                            __half* __restrict__ h2h, float* __restrict__ next_hidden)
{
    int gt = blockIdx.x * blockDim.x + threadIdx.x;
    int d = gt & (D_ - 1);
    int chunk = (gt >> 10) & (NCHUNK - 1);
    int b = gt >> 16;
    float h = carry[(b * NCHUNK + chunk) * D_ + d];
    for (int s = 0; s < CLEN; s++) {
        int t = chunk * CLEN + s;
        size_t o = (size_t)(b * S_ + t) * D_ + d;
        h = cb[o] * h + vb[o];
        float hv = h + __half2float(h1h[o]);
        h2h[o] = __float2half_rn(hv);
        if (t == S_ - 1) next_hidden[b * D_ + d] = h;
    }
}

// ---------------- loss reduction over N-tile partials -----------------------
__global__ void loss_reduce(const float2* __restrict__ part,
                            const float* __restrict__ logits,
                            const int* __restrict__ x, float* __restrict__ lp)
{
    int tk = blockIdx.x;
    int tid = threadIdx.x;       // 128 threads
    float m = -INFINITY, s = 0.f;
    for (int i = tid; i < NT_LOG; i += 128) {
        float2 p = part[(size_t)tk * NT_LOG + i];
        lmerge(m, s, p.x, p.y);
    }
    __shared__ float sm[128], ssum[128];
    sm[tid] = m; ssum[tid] = s; __syncthreads();
    for (int st = 64; st > 0; st >>= 1) {
        if (tid < st) {
            lmerge(sm[tid], ssum[tid], sm[tid + st], ssum[tid + st]);
        }
        __syncthreads();
    }
    if (tid == 0) {
        int b = tk >> 11, t = tk & 2047;
        int lab = x[b * S1_ + t + 1];
        lp[tk] = logits[(size_t)tk * V_ + lab] - (sm[0] + logf(ssum[0]));
    }
}

__global__ void loss_final(const float* __restrict__ lp, float* __restrict__ outp)
{
    int tid = threadIdx.x;
    float s = 0.f;
    for (int i = tid; i < T_; i += 256) s += lp[i];
    __shared__ float red[256];
    red[tid] = s; __syncthreads();
    for (int st = 128; st > 0; st >>= 1) {
        if (tid < st) red[tid] += red[tid + st];
        __syncthreads();
    }
    if (tid == 0) outp[0] = -red[0] / (float)T_;
}

// ---------------- launch ----------------------------------------------------
extern "C" void kernel_launch(void* const* d_in, const int* in_sizes, int n_in,
                              void* d_out, int out_size)
{
    const int*   x       = (const int*)  d_in[0];
    const float* emb     = (const float*)d_in[1];
    const float* gamma1  = (const float*)d_in[2];
    const float* W_hg    = (const float*)d_in[3];
    const float* W1      = (const float*)d_in[4];
    const float* b1      = (const float*)d_in[5];
    const float* W2      = (const float*)d_in[6];
    const float* b2      = (const float*)d_in[7];
    const float* gamma2  = (const float*)d_in[8];
    const float* Wlog    = (const float*)d_in[9];
    float* out = (float*)d_out;

    float *hg, *cb, *vb, *Ac, *Bc, *carry, *h3, *lp;
    float2* lpart;
    __half *h1h, *h2h, *mlp1h, *h4h, *whgT, *w1T, *w2T, *wlogT;
    cudaGetSymbolAddress((void**)&h1h,   g_h1h);
    cudaGetSymbolAddress((void**)&hg,    g_hg);
    cudaGetSymbolAddress((void**)&cb,    g_cb);
    cudaGetSymbolAddress((void**)&vb,    g_vb);
    cudaGetSymbolAddress((void**)&Ac,    g_Ac);
    cudaGetSymbolAddress((void**)&Bc,    g_Bc);
    cudaGetSymbolAddress((void**)&carry, g_carry);
    cudaGetSymbolAddress((void**)&h2h,   g_h2h);
    cudaGetSymbolAddress((void**)&mlp1h, g_mlp1h);
    cudaGetSymbolAddress((void**)&h3,    g_h3);
    cudaGetSymbolAddress((void**)&h4h,   g_h4h);
    cudaGetSymbolAddress((void**)&lp,    g_lp);
    cudaGetSymbolAddress((void**)&lpart, g_lpart);
    cudaGetSymbolAddress((void**)&whgT,  g_whgT);
    cudaGetSymbolAddress((void**)&w1T,   g_w1T);
    cudaGetSymbolAddress((void**)&w2T,   g_w2T);
    cudaGetSymbolAddress((void**)&wlogT, g_wlogT);

    const int smem_bytes = STAGES * STG_HALVES * (int)sizeof(__half);   // 110592
    static bool init_done = false;
    static cudaStream_t s2;
    static cudaEvent_t ev_fork, ev_whg, ev_join;
    if (!init_done) {
        cudaFuncSetAttribute((const void*)gemm_f16<0,0>,
                             cudaFuncAttributeMaxDynamicSharedMemorySize, smem_bytes);
        cudaFuncSetAttribute((const void*)gemm_f16<0,1>,
                             cudaFuncAttributeMaxDynamicSharedMemorySize, smem_bytes);
        cudaFuncSetAttribute((const void*)gemm_f16<1,0>,
                             cudaFuncAttributeMaxDynamicSharedMemorySize, smem_bytes);
        cudaStreamCreateWithFlags(&s2, cudaStreamNonBlocking);
        cudaEventCreateWithFlags(&ev_fork, cudaEventDisableTiming);
        cudaEventCreateWithFlags(&ev_whg,  cudaEventDisableTiming);
        cudaEventCreateWithFlags(&ev_join, cudaEventDisableTiming);
        init_done = true;
    }

    float* logits      = out + 1;
    float* next_hidden = out + 1 + (size_t)T_ * V_;

    dim3 tb(32, 8);

    // fork: ALL weight conversions on s2, overlapped with embed/scan chain
    cudaEventRecord(ev_fork, 0);
    cudaStreamWaitEvent(s2, ev_fork, 0);
    transposeW<<<dim3((2 * D_) / 32, D_ / 32), tb, 0, s2>>>(W_hg, whgT, D_, 2 * D_, 2 * D_);
    cudaEventRecord(ev_whg, s2);
    transposeW<<<dim3((4 * D_) / 32, D_ / 32), tb, 0, s2>>>(W1,   w1T,  D_,     4 * D_, 4 * D_);
    transposeW<<<dim3(D_ / 32, (4 * D_) / 32), tb, 0, s2>>>(W2,   w2T,  4 * D_, D_,     D_);
    transposeW<<<dim3(VP_ / 32, D_ / 32),      tb, 0, s2>>>(Wlog, wlogT, D_,    V_,     VP_);
    cudaEventRecord(ev_join, s2);

    embed_rms<<<T_, 256>>>(x, emb, gamma1, h1h);

    // hg = h1 @ W_hg   [4096 x 2048] fp32 out  (needs whgT)
    cudaStreamWaitEvent(0, ev_whg, 0);
    gemm_f16<0,0><<<dim3(T_ / BM, (2 * D_) / BN), 256, smem_bytes>>>(
        h1h, whgT, hg, T_, 2 * D_, D_, nullptr, nullptr, 0, 0, nullptr);

    scan_phase1<<<(B_ * NCHUNK * D_) / 256, 256>>>(hg, cb, vb, Ac, Bc);
    scan_phase2<<<(B_ * D_) / 256, 256>>>(Ac, Bc, carry);
    scan_phase3<<<(B_ * NCHUNK * D_) / 256, 256>>>(cb, vb, carry, h1h, h2h, next_hidden);

    // join before first use of w1T/w2T/wlogT
    cudaStreamWaitEvent(0, ev_join, 0);

    // mlp1 = gelu(h2 @ W1 + b1)   [4096 x 4096] fp16 out
    gemm_f16<0,0><<<dim3(T_ / BM, (4 * D_) / BN), 256, smem_bytes>>>(
        h2h, w1T, mlp1h, T_, 4 * D_, D_, b1, nullptr, 1, 1, nullptr);

    // h3 = mlp1 @ W2 + b2 + h2    [4096 x 1024] fp32 out, fp16 residual
    gemm_f16<0,1><<<dim3(T_ / BM, D_ / BN), 256, smem_bytes>>>(
        mlp1h, w2T, h3, T_, D_, 4 * D_, b2, h2h, 0, 0, nullptr);

    rms_rows<<<T_, 256>>>(h3, gamma2, h4h);

    // logits = h4 @ W_logits  [4096 x 50257] fp32 out + inline loss partials
    gemm_f16<1,0><<<dim3(T_ / BM, VP_ / BN), 256, smem_bytes>>>(
        h4h, wlogT, logits, T_, V_, D_, nullptr, nullptr, 0, 0, lpart);

    loss_reduce<<<T_, 128>>>(lpart, logits, x, lp);
    loss_final<<<1, 256>>>(lp, out);
}